// round 5
// baseline (speedup 1.0000x reference)
#include <cuda_runtime.h>
#include <cuda_fp16.h>
#include <stdint.h>

#define VOCAB  30522
#define HIDDEN 768
#define EMBED  512
#define BATCH  16
#define SEQ    512
#define WSUB   4
#define MROWS  (BATCH*SEQ)     // 8192

#define BK     64              // k per stage (64 halves = 128B rows)
#define NCH    (HIDDEN/BK)     // 12 k-chunks
#define MT     128
#define NT     128
#define STAGES 3
#define A_ST   (MT*128)        // 16 KB
#define B_ST   (NT*128)        // 16 KB
#define STG_B  (A_ST + B_ST)   // 32 KB
#define SMEM_TOTAL (STAGES*STG_B + 128)

// ---- scratch (__device__ globals: allocation-free) ----
__device__ __align__(256) __half g_A [(size_t)MROWS*HIDDEN];   // pooled, compacted, fp16
__device__ __align__(256) __half g_Wt[(size_t)EMBED*HIDDEN];   // W^T  [N=512][K=768] fp16
__device__ int   g_dest[MROWS];
__device__ int   g_lens[BATCH];
__device__ float g_padout[EMBED];

// ================= PTX helpers =================
__device__ __forceinline__ uint32_t smem_u32(const void* p) {
    uint32_t a;
    asm("{ .reg .u64 t; cvta.to.shared.u64 t, %1; cvt.u32.u64 %0, t; }" : "=r"(a) : "l"(p));
    return a;
}
#define CP16(dst, src)  asm volatile("cp.async.cg.shared.global [%0], [%1], 16;" :: "r"(dst), "l"(src))
#define CP_COMMIT()     asm volatile("cp.async.commit_group;" ::: "memory")
#define CP_WAIT2()      asm volatile("cp.async.wait_group 2;" ::: "memory")

__device__ __forceinline__ void ldsm_x4(uint32_t* r, uint32_t addr) {
    asm volatile("ldmatrix.sync.aligned.m8n8.x4.shared.b16 {%0,%1,%2,%3}, [%4];"
        : "=r"(r[0]), "=r"(r[1]), "=r"(r[2]), "=r"(r[3]) : "r"(addr));
}
__device__ __forceinline__ void mma16816(float* d, const uint32_t* a, uint32_t b0, uint32_t b1) {
    asm volatile("mma.sync.aligned.m16n8k16.row.col.f32.f16.f16.f32 "
        "{%0,%1,%2,%3}, {%4,%5,%6,%7}, {%8,%9}, {%0,%1,%2,%3};"
        : "+f"(d[0]), "+f"(d[1]), "+f"(d[2]), "+f"(d[3])
        : "r"(a[0]), "r"(a[1]), "r"(a[2]), "r"(a[3]), "r"(b0), "r"(b1));
}

// ============================================================
// Kernel 1 (fused prep): role dispatch on blockIdx.x, 512 thr/blk
//   [0,16)    : per-batch stable compaction scan
//   [16,400)  : W transpose+convert -> g_Wt [512][768] fp16
//   [400,404) : pad row = leaky(embed[words[2047]] @ W + b), fp32 exact
// ============================================================
#define PREP_SCAN   16
#define PREP_WT     (PREP_SCAN + 384)
#define PREP_BLKS   (PREP_WT + 4)

__global__ __launch_bounds__(512)
void prep_kernel(const int* __restrict__ words,
                 const float* __restrict__ et,
                 const float* __restrict__ Wf,
                 const float* __restrict__ bias) {
    const int bid = blockIdx.x, tid = threadIdx.x;

    if (bid < PREP_SCAN) {
        // ---- scan: one batch per block ----
        __shared__ int buf[SEQ];
        const int b = bid, s = tid;
        const int* wp = words + ((size_t)(b * SEQ + s)) * WSUB;
        int v = (wp[0] != 0) || (wp[1] != 0) || (wp[2] != 0) || (wp[3] != 0);
        buf[s] = v;
        __syncthreads();
        #pragma unroll
        for (int off = 1; off < SEQ; off <<= 1) {
            int t = (s >= off) ? buf[s - off] : 0;
            __syncthreads();
            buf[s] += t;
            __syncthreads();
        }
        int incl = buf[s];
        g_dest[b * SEQ + s] = v ? (incl - 1) : -1;
        if (s == SEQ - 1) g_lens[b] = incl;
    } else if (bid < PREP_WT) {
        // ---- wtrans: 32x32 tile per block, (32,16) layout ----
        __shared__ float sh[32][33];
        const int b2 = bid - PREP_SCAN;
        const int ks = (b2 % (HIDDEN / 32)) * 32;
        const int ns = (b2 / (HIDDEN / 32)) * 32;
        const int tx = tid & 31, ty = tid >> 5;   // 32 x 16
        #pragma unroll
        for (int i = 0; i < 2; i++)
            sh[ty + 16 * i][tx] = Wf[(size_t)(ks + ty + 16 * i) * EMBED + ns + tx];
        __syncthreads();
        #pragma unroll
        for (int i = 0; i < 2; i++) {
            const int n = ns + ty + 16 * i, k = ks + tx;
            g_Wt[(size_t)n * HIDDEN + k] = __float2half(sh[tx][ty + 16 * i]);
        }
    } else {
        // ---- padout: 4 blocks x 128 cols, 4 k-slices of 192 ----
        __shared__ float part[4][128];
        const int pb = bid - PREP_WT;
        const int c = tid & 127, slice = tid >> 7;
        const int col = pb * 128 + c;
        const int pad_id = words[(SEQ - 1) * WSUB + (WSUB - 1)];
        const float* e = et + (size_t)pad_id * HIDDEN + slice * 192;
        const float* w = Wf + (size_t)(slice * 192) * EMBED + col;
        float p = 0.f;
        #pragma unroll 4
        for (int k = 0; k < 192; k++)
            p = fmaf(__ldg(e + k), __ldg(w + (size_t)k * EMBED), p);
        part[slice][c] = p;
        __syncthreads();
        if (slice == 0) {
            float x = part[0][c] + part[1][c] + part[2][c] + part[3][c] + bias[col];
            g_padout[col] = (x >= 0.f) ? x : 0.1f * x;
        }
    }
}

// ============================================================
// Kernel 2: gather + masked mean-pool + compaction -> fp16
// warp-per-word: 24 independent LDG.128 per lane. grid=1024, block=256
// ============================================================
__global__ __launch_bounds__(256)
void pool_kernel(const int* __restrict__ words,
                 const float* __restrict__ et) {
    const int lane = threadIdx.x & 31, w = threadIdx.x >> 5;
    const int idx = blockIdx.x * 8 + w;             // word index
    const int d = g_dest[idx];
    if (d < 0) return;
    const int* wp = words + (size_t)idx * WSUB;
    const int i0 = wp[0], i1 = wp[1], i2 = wp[2], i3 = wp[3];
    const float cnt = (float)((i0 != 0) + (i1 != 0) + (i2 != 0) + (i3 != 0));
    const float inv = 1.0f / cnt;

    const float* r0 = et + (size_t)i0 * HIDDEN + lane * 4;
    const float* r1 = et + (size_t)i1 * HIDDEN + lane * 4;
    const float* r2 = et + (size_t)i2 * HIDDEN + lane * 4;
    const float* r3 = et + (size_t)i3 * HIDDEN + lane * 4;

    float4 acc[6];
    #pragma unroll
    for (int c = 0; c < 6; c++) {
        float4 s = make_float4(0.f, 0.f, 0.f, 0.f);
        if (i0 != 0) { float4 v = *(const float4*)(r0 + c * 128); s.x += v.x; s.y += v.y; s.z += v.z; s.w += v.w; }
        if (i1 != 0) { float4 v = *(const float4*)(r1 + c * 128); s.x += v.x; s.y += v.y; s.z += v.z; s.w += v.w; }
        if (i2 != 0) { float4 v = *(const float4*)(r2 + c * 128); s.x += v.x; s.y += v.y; s.z += v.z; s.w += v.w; }
        if (i3 != 0) { float4 v = *(const float4*)(r3 + c * 128); s.x += v.x; s.y += v.y; s.z += v.z; s.w += v.w; }
        acc[c] = s;
    }

    const int row = (idx & ~(SEQ - 1)) + d;
    __half* dst = g_A + (size_t)row * HIDDEN + lane * 4;
    #pragma unroll
    for (int c = 0; c < 6; c++) {
        __half2 p0, p1;
        p0.x = __float2half(acc[c].x * inv); p0.y = __float2half(acc[c].y * inv);
        p1.x = __float2half(acc[c].z * inv); p1.y = __float2half(acc[c].w * inv);
        __half2* o = (__half2*)(dst + c * 128);
        o[0] = p0; o[1] = p1;
    }
}

// ============================================================
// Kernel 3: fp16 HMMA GEMM [8192x512, K=768] + fused epilogue
// CTA 128x128, 8 warps (2x4) of 64x32, BK=64, 3-stage cp.async
// grid=(4,64), block=256, 2 CTAs/SM
// ============================================================
__device__ __forceinline__ void load_stage(int j, int tid, uint32_t data0,
                                           int bm0, int bn0) {
    const int s = j % STAGES;
    const int kk = j * BK;
    const uint32_t abase = data0 + s * STG_B;
    const uint32_t bbase = abase + A_ST;
    #pragma unroll
    for (int it = 0; it < 4; it++) {
        int c = tid + it * 256;
        int r = c >> 3, c16 = c & 7;
        const void* src = g_A + (size_t)(bm0 + r) * HIDDEN + kk + c16 * 8;
        uint32_t dst = abase + (uint32_t)(r * 128) + (((uint32_t)c16 * 16) ^ ((uint32_t)(r & 7) << 4));
        CP16(dst, src);
    }
    #pragma unroll
    for (int it = 0; it < 4; it++) {
        int c = tid + it * 256;
        int r = c >> 3, c16 = c & 7;
        const void* src = g_Wt + (size_t)(bn0 + r) * HIDDEN + kk + c16 * 8;
        uint32_t dst = bbase + (uint32_t)(r * 128) + (((uint32_t)c16 * 16) ^ ((uint32_t)(r & 7) << 4));
        CP16(dst, src);
    }
}

__global__ __launch_bounds__(256, 2)
void gemm_hmma_kernel(const float* __restrict__ bias, float* __restrict__ out) {
    extern __shared__ char smem[];
    const uint32_t data0 = (smem_u32(smem) + 127u) & ~127u;
    const int tid = threadIdx.x, lane = tid & 31, wid = tid >> 5;
    const int wm = wid & 1, wn = wid >> 1;            // 2 x 4 warp grid
    const int bm0 = blockIdx.y * MT, bn0 = blockIdx.x * NT;

    const int a_moff = (lane & 7) + ((lane >> 3) & 1) * 8;
    const int a_k8   = lane >> 4;
    const int b_noff = (lane & 7) + (lane >> 4) * 8;
    const int b_k8   = (lane >> 3) & 1;
    const uint32_t a_row = (uint32_t)((wm * 64 + a_moff) * 128);
    const uint32_t b_row = (uint32_t)(A_ST + (wn * 32 + b_noff) * 128);
    uint32_t akx[4], bkx[4];
    #pragma unroll
    for (int ks = 0; ks < 4; ks++) {
        akx[ks] = ((uint32_t)((ks * 2 + a_k8) * 16)) ^ ((uint32_t)(a_moff & 7) << 4);
        bkx[ks] = ((uint32_t)((ks * 2 + b_k8) * 16)) ^ ((uint32_t)(b_noff & 7) << 4);
    }

    float acc[4][4][4];
    #pragma unroll
    for (int i = 0; i < 4; i++)
        #pragma unroll
        for (int j = 0; j < 4; j++)
            #pragma unroll
            for (int q = 0; q < 4; q++) acc[i][j][q] = 0.f;

    load_stage(0, tid, data0, bm0, bn0); CP_COMMIT();
    load_stage(1, tid, data0, bm0, bn0); CP_COMMIT();

    for (int i = 0; i < NCH; i++) {
        if (i + 2 < NCH) load_stage(i + 2, tid, data0, bm0, bn0);
        CP_COMMIT();
        CP_WAIT2();
        __syncthreads();

        const uint32_t sa = data0 + (i % STAGES) * STG_B;
        #pragma unroll
        for (int ks = 0; ks < 4; ks++) {
            uint32_t a[4][4], b[2][4];
            #pragma unroll
            for (int mt = 0; mt < 4; mt++)
                ldsm_x4(a[mt], sa + a_row + (uint32_t)(mt * 2048) + akx[ks]);
            #pragma unroll
            for (int np = 0; np < 2; np++)
                ldsm_x4(b[np], sa + b_row + (uint32_t)(np * 2048) + bkx[ks]);
            #pragma unroll
            for (int mt = 0; mt < 4; mt++) {
                #pragma unroll
                for (int np = 0; np < 2; np++) {
                    mma16816(acc[mt][np * 2 + 0], a[mt], b[np][0], b[np][1]);
                    mma16816(acc[mt][np * 2 + 1], a[mt], b[np][2], b[np][3]);
                }
            }
        }
        __syncthreads();
    }

    // ---- epilogue: bias + leaky on valid rows, pad row on tail ----
    const int coln = bn0 + wn * 32 + (lane & 3) * 2;
    float2 bj[4], pj[4];
    #pragma unroll
    for (int nt = 0; nt < 4; nt++) {
        const int c = coln + nt * 8;
        bj[nt] = make_float2(__ldg(bias + c), __ldg(bias + c + 1));
        pj[nt] = make_float2(g_padout[c], g_padout[c + 1]);
    }
    #pragma unroll
    for (int mt = 0; mt < 4; mt++) {
        const int r0 = bm0 + wm * 64 + mt * 16 + (lane >> 2);
        const int len = g_lens[r0 >> 9];
        const bool v0 = (r0 & (SEQ - 1)) < len;
        const bool v1 = ((r0 + 8) & (SEQ - 1)) < len;
        #pragma unroll
        for (int nt = 0; nt < 4; nt++) {
            const int c = coln + nt * 8;
            float2 o0, o1;
            if (v0) {
                float x = acc[mt][nt][0] + bj[nt].x, y = acc[mt][nt][1] + bj[nt].y;
                o0 = make_float2(fmaxf(x, 0.1f * x), fmaxf(y, 0.1f * y));
            } else o0 = pj[nt];
            if (v1) {
                float x = acc[mt][nt][2] + bj[nt].x, y = acc[mt][nt][3] + bj[nt].y;
                o1 = make_float2(fmaxf(x, 0.1f * x), fmaxf(y, 0.1f * y));
            } else o1 = pj[nt];
            *(float2*)(out + (size_t)r0 * EMBED + c)       = o0;
            *(float2*)(out + (size_t)(r0 + 8) * EMBED + c) = o1;
        }
    }
}

// ============================================================
extern "C" void kernel_launch(void* const* d_in, const int* in_sizes, int n_in,
                              void* d_out, int out_size) {
    const int*   words = (const int*)  d_in[0];
    const float* et    = (const float*)d_in[1];
    const float* wf    = (const float*)d_in[2];
    const float* bf    = (const float*)d_in[3];
    float* out = (float*)d_out;

    cudaFuncSetAttribute(gemm_hmma_kernel,
                         cudaFuncAttributeMaxDynamicSharedMemorySize, SMEM_TOTAL);

    prep_kernel<<<PREP_BLKS, 512>>>(words, et, wf, bf);
    pool_kernel<<<MROWS / 8, 256>>>(words, et);
    gemm_hmma_kernel<<<dim3(EMBED / NT, MROWS / MT), 256, SMEM_TOTAL>>>(bf, out);
}

// round 6
// speedup vs baseline: 1.3529x; 1.3529x over previous
#include <cuda_runtime.h>
#include <cuda_fp16.h>
#include <stdint.h>

#define VOCAB  30522
#define HIDDEN 768
#define EMBED  512
#define BATCH  16
#define SEQ    512
#define WSUB   4
#define MROWS  (BATCH*SEQ)     // 8192

#define BK     64              // k per stage (64 halves = 128B rows)
#define NCH    (HIDDEN/BK)     // 12 k-chunks
#define MT     128
#define NT     128
#define STAGES 3
#define A_ST   (MT*128)        // 16 KB
#define B_ST   (NT*128)        // 16 KB
#define STG_B  (A_ST + B_ST)   // 32 KB
#define SMEM_TOTAL (STAGES*STG_B + 128)

// ---- scratch (__device__ globals: allocation-free) ----
__device__ __align__(256) __half g_A [(size_t)MROWS*HIDDEN];   // pooled, compacted, fp16
__device__ __align__(256) __half g_Wt[(size_t)EMBED*HIDDEN];   // W^T  [N=512][K=768] fp16
__device__ int   g_dest[MROWS];
__device__ int   g_lens[BATCH];
__device__ float g_padout[EMBED];

// ================= PTX helpers =================
__device__ __forceinline__ uint32_t smem_u32(const void* p) {
    uint32_t a;
    asm("{ .reg .u64 t; cvta.to.shared.u64 t, %1; cvt.u32.u64 %0, t; }" : "=r"(a) : "l"(p));
    return a;
}
#define CP16(dst, src)  asm volatile("cp.async.cg.shared.global [%0], [%1], 16;" :: "r"(dst), "l"(src))
#define CP_COMMIT()     asm volatile("cp.async.commit_group;" ::: "memory")
#define CP_WAIT2()      asm volatile("cp.async.wait_group 2;" ::: "memory")

__device__ __forceinline__ void ldsm_x4(uint32_t* r, uint32_t addr) {
    asm volatile("ldmatrix.sync.aligned.m8n8.x4.shared.b16 {%0,%1,%2,%3}, [%4];"
        : "=r"(r[0]), "=r"(r[1]), "=r"(r[2]), "=r"(r[3]) : "r"(addr));
}
__device__ __forceinline__ void mma16816(float* d, const uint32_t* a, uint32_t b0, uint32_t b1) {
    asm volatile("mma.sync.aligned.m16n8k16.row.col.f32.f16.f16.f32 "
        "{%0,%1,%2,%3}, {%4,%5,%6,%7}, {%8,%9}, {%0,%1,%2,%3};"
        : "+f"(d[0]), "+f"(d[1]), "+f"(d[2]), "+f"(d[3])
        : "r"(a[0]), "r"(a[1]), "r"(a[2]), "r"(a[3]), "r"(b0), "r"(b1));
}

// ============================================================
// Kernel 1 (fused prep): role dispatch on blockIdx.x, 512 thr/blk
//   [0,16)    : per-batch stable compaction scan
//   [16,400)  : W transpose+convert -> g_Wt [512][768] fp16
//   [400,416) : pad row = leaky(embed[words[2047]] @ W + b), fp32,
//               32 cols x 16 k-slices per block (latency-tolerant)
// ============================================================
#define PREP_SCAN   16
#define PREP_WT     (PREP_SCAN + 384)
#define PREP_BLKS   (PREP_WT + 16)

__global__ __launch_bounds__(512)
void prep_kernel(const int* __restrict__ words,
                 const float* __restrict__ et,
                 const float* __restrict__ Wf,
                 const float* __restrict__ bias) {
    const int bid = blockIdx.x, tid = threadIdx.x;

    if (bid < PREP_SCAN) {
        // ---- scan: one batch per block ----
        __shared__ int buf[SEQ];
        const int b = bid, s = tid;
        const int* wp = words + ((size_t)(b * SEQ + s)) * WSUB;
        int v = (wp[0] != 0) || (wp[1] != 0) || (wp[2] != 0) || (wp[3] != 0);
        buf[s] = v;
        __syncthreads();
        #pragma unroll
        for (int off = 1; off < SEQ; off <<= 1) {
            int t = (s >= off) ? buf[s - off] : 0;
            __syncthreads();
            buf[s] += t;
            __syncthreads();
        }
        int incl = buf[s];
        g_dest[b * SEQ + s] = v ? (incl - 1) : -1;
        if (s == SEQ - 1) g_lens[b] = incl;
    } else if (bid < PREP_WT) {
        // ---- wtrans: 32x32 tile per block, (32,16) layout ----
        __shared__ float sh[32][33];
        const int b2 = bid - PREP_SCAN;
        const int ks = (b2 % (HIDDEN / 32)) * 32;
        const int ns = (b2 / (HIDDEN / 32)) * 32;
        const int tx = tid & 31, ty = tid >> 5;   // 32 x 16
        #pragma unroll
        for (int i = 0; i < 2; i++)
            sh[ty + 16 * i][tx] = Wf[(size_t)(ks + ty + 16 * i) * EMBED + ns + tx];
        __syncthreads();
        #pragma unroll
        for (int i = 0; i < 2; i++) {
            const int n = ns + ty + 16 * i, k = ks + tx;
            g_Wt[(size_t)n * HIDDEN + k] = __float2half(sh[tx][ty + 16 * i]);
        }
    } else {
        // ---- padout: 16 blocks, each 32 cols x 16 k-slices of 48 ----
        __shared__ float part[16][33];
        const int pb = bid - PREP_WT;
        const int c = tid & 31, slice = tid >> 5;     // 32 cols x 16 slices
        const int col = pb * 32 + c;
        const int pad_id = words[(SEQ - 1) * WSUB + (WSUB - 1)];
        const float* e = et + (size_t)pad_id * HIDDEN + slice * 48;
        const float* w = Wf + (size_t)(slice * 48) * EMBED + col;
        float p = 0.f;
        #pragma unroll
        for (int k = 0; k < 48; k++)
            p = fmaf(__ldg(e + k), __ldg(w + (size_t)k * EMBED), p);
        part[slice][c] = p;
        __syncthreads();
        if (slice == 0) {
            float s = 0.f;
            #pragma unroll
            for (int i = 0; i < 16; i++) s += part[i][c];
            float x = s + bias[col];
            g_padout[col] = (x >= 0.f) ? x : 0.1f * x;
        }
    }
}

// ============================================================
// Kernel 2: gather + masked mean-pool + compaction -> fp16
// warp-per-word: 24 independent LDG.128 per lane. grid=1024, block=256
// ============================================================
__global__ __launch_bounds__(256)
void pool_kernel(const int* __restrict__ words,
                 const float* __restrict__ et) {
    const int lane = threadIdx.x & 31, w = threadIdx.x >> 5;
    const int idx = blockIdx.x * 8 + w;             // word index
    const int d = g_dest[idx];
    if (d < 0) return;
    const int* wp = words + (size_t)idx * WSUB;
    const int i0 = wp[0], i1 = wp[1], i2 = wp[2], i3 = wp[3];
    const float cnt = (float)((i0 != 0) + (i1 != 0) + (i2 != 0) + (i3 != 0));
    const float inv = 1.0f / cnt;

    const float* r0 = et + (size_t)i0 * HIDDEN + lane * 4;
    const float* r1 = et + (size_t)i1 * HIDDEN + lane * 4;
    const float* r2 = et + (size_t)i2 * HIDDEN + lane * 4;
    const float* r3 = et + (size_t)i3 * HIDDEN + lane * 4;

    float4 acc[6];
    #pragma unroll
    for (int c = 0; c < 6; c++) {
        float4 s = make_float4(0.f, 0.f, 0.f, 0.f);
        if (i0 != 0) { float4 v = *(const float4*)(r0 + c * 128); s.x += v.x; s.y += v.y; s.z += v.z; s.w += v.w; }
        if (i1 != 0) { float4 v = *(const float4*)(r1 + c * 128); s.x += v.x; s.y += v.y; s.z += v.z; s.w += v.w; }
        if (i2 != 0) { float4 v = *(const float4*)(r2 + c * 128); s.x += v.x; s.y += v.y; s.z += v.z; s.w += v.w; }
        if (i3 != 0) { float4 v = *(const float4*)(r3 + c * 128); s.x += v.x; s.y += v.y; s.z += v.z; s.w += v.w; }
        acc[c] = s;
    }

    const int row = (idx & ~(SEQ - 1)) + d;
    __half* dst = g_A + (size_t)row * HIDDEN + lane * 4;
    #pragma unroll
    for (int c = 0; c < 6; c++) {
        __half2 p0, p1;
        p0.x = __float2half(acc[c].x * inv); p0.y = __float2half(acc[c].y * inv);
        p1.x = __float2half(acc[c].z * inv); p1.y = __float2half(acc[c].w * inv);
        __half2* o = (__half2*)(dst + c * 128);
        o[0] = p0; o[1] = p1;
    }
}

// ============================================================
// Kernel 3: fp16 HMMA GEMM [8192x512, K=768] + fused epilogue
// CTA 128x128, 8 warps (2x4) of 64x32, BK=64, 3-stage cp.async
// grid=(4,64), block=256, 2 CTAs/SM
// ============================================================
__device__ __forceinline__ void load_stage(int j, int tid, uint32_t data0,
                                           int bm0, int bn0) {
    const int s = j % STAGES;
    const int kk = j * BK;
    const uint32_t abase = data0 + s * STG_B;
    const uint32_t bbase = abase + A_ST;
    #pragma unroll
    for (int it = 0; it < 4; it++) {
        int c = tid + it * 256;
        int r = c >> 3, c16 = c & 7;
        const void* src = g_A + (size_t)(bm0 + r) * HIDDEN + kk + c16 * 8;
        uint32_t dst = abase + (uint32_t)(r * 128) + (((uint32_t)c16 * 16) ^ ((uint32_t)(r & 7) << 4));
        CP16(dst, src);
    }
    #pragma unroll
    for (int it = 0; it < 4; it++) {
        int c = tid + it * 256;
        int r = c >> 3, c16 = c & 7;
        const void* src = g_Wt + (size_t)(bn0 + r) * HIDDEN + kk + c16 * 8;
        uint32_t dst = bbase + (uint32_t)(r * 128) + (((uint32_t)c16 * 16) ^ ((uint32_t)(r & 7) << 4));
        CP16(dst, src);
    }
}

__global__ __launch_bounds__(256, 2)
void gemm_hmma_kernel(const float* __restrict__ bias, float* __restrict__ out) {
    extern __shared__ char smem[];
    const uint32_t data0 = (smem_u32(smem) + 127u) & ~127u;
    const int tid = threadIdx.x, lane = tid & 31, wid = tid >> 5;
    const int wm = wid & 1, wn = wid >> 1;            // 2 x 4 warp grid
    const int bm0 = blockIdx.y * MT, bn0 = blockIdx.x * NT;

    const int a_moff = (lane & 7) + ((lane >> 3) & 1) * 8;
    const int a_k8   = lane >> 4;
    const int b_noff = (lane & 7) + (lane >> 4) * 8;
    const int b_k8   = (lane >> 3) & 1;
    const uint32_t a_row = (uint32_t)((wm * 64 + a_moff) * 128);
    const uint32_t b_row = (uint32_t)(A_ST + (wn * 32 + b_noff) * 128);
    uint32_t akx[4], bkx[4];
    #pragma unroll
    for (int ks = 0; ks < 4; ks++) {
        akx[ks] = ((uint32_t)((ks * 2 + a_k8) * 16)) ^ ((uint32_t)(a_moff & 7) << 4);
        bkx[ks] = ((uint32_t)((ks * 2 + b_k8) * 16)) ^ ((uint32_t)(b_noff & 7) << 4);
    }

    float acc[4][4][4];
    #pragma unroll
    for (int i = 0; i < 4; i++)
        #pragma unroll
        for (int j = 0; j < 4; j++)
            #pragma unroll
            for (int q = 0; q < 4; q++) acc[i][j][q] = 0.f;

    load_stage(0, tid, data0, bm0, bn0); CP_COMMIT();
    load_stage(1, tid, data0, bm0, bn0); CP_COMMIT();

    for (int i = 0; i < NCH; i++) {
        if (i + 2 < NCH) load_stage(i + 2, tid, data0, bm0, bn0);
        CP_COMMIT();
        CP_WAIT2();
        __syncthreads();

        const uint32_t sa = data0 + (i % STAGES) * STG_B;
        #pragma unroll
        for (int ks = 0; ks < 4; ks++) {
            uint32_t a[4][4], b[2][4];
            #pragma unroll
            for (int mt = 0; mt < 4; mt++)
                ldsm_x4(a[mt], sa + a_row + (uint32_t)(mt * 2048) + akx[ks]);
            #pragma unroll
            for (int np = 0; np < 2; np++)
                ldsm_x4(b[np], sa + b_row + (uint32_t)(np * 2048) + bkx[ks]);
            #pragma unroll
            for (int mt = 0; mt < 4; mt++) {
                #pragma unroll
                for (int np = 0; np < 2; np++) {
                    mma16816(acc[mt][np * 2 + 0], a[mt], b[np][0], b[np][1]);
                    mma16816(acc[mt][np * 2 + 1], a[mt], b[np][2], b[np][3]);
                }
            }
        }
        __syncthreads();
    }

    // ---- epilogue: bias + leaky on valid rows, pad row on tail ----
    const int coln = bn0 + wn * 32 + (lane & 3) * 2;
    float2 bj[4], pj[4];
    #pragma unroll
    for (int nt = 0; nt < 4; nt++) {
        const int c = coln + nt * 8;
        bj[nt] = make_float2(__ldg(bias + c), __ldg(bias + c + 1));
        pj[nt] = make_float2(g_padout[c], g_padout[c + 1]);
    }
    #pragma unroll
    for (int mt = 0; mt < 4; mt++) {
        const int r0 = bm0 + wm * 64 + mt * 16 + (lane >> 2);
        const int len = g_lens[r0 >> 9];
        const bool v0 = (r0 & (SEQ - 1)) < len;
        const bool v1 = ((r0 + 8) & (SEQ - 1)) < len;
        #pragma unroll
        for (int nt = 0; nt < 4; nt++) {
            const int c = coln + nt * 8;
            float2 o0, o1;
            if (v0) {
                float x = acc[mt][nt][0] + bj[nt].x, y = acc[mt][nt][1] + bj[nt].y;
                o0 = make_float2(fmaxf(x, 0.1f * x), fmaxf(y, 0.1f * y));
            } else o0 = pj[nt];
            if (v1) {
                float x = acc[mt][nt][2] + bj[nt].x, y = acc[mt][nt][3] + bj[nt].y;
                o1 = make_float2(fmaxf(x, 0.1f * x), fmaxf(y, 0.1f * y));
            } else o1 = pj[nt];
            *(float2*)(out + (size_t)r0 * EMBED + c)       = o0;
            *(float2*)(out + (size_t)(r0 + 8) * EMBED + c) = o1;
        }
    }
}

// ============================================================
extern "C" void kernel_launch(void* const* d_in, const int* in_sizes, int n_in,
                              void* d_out, int out_size) {
    const int*   words = (const int*)  d_in[0];
    const float* et    = (const float*)d_in[1];
    const float* wf    = (const float*)d_in[2];
    const float* bf    = (const float*)d_in[3];
    float* out = (float*)d_out;

    cudaFuncSetAttribute(gemm_hmma_kernel,
                         cudaFuncAttributeMaxDynamicSharedMemorySize, SMEM_TOTAL);

    prep_kernel<<<PREP_BLKS, 512>>>(words, et, wf, bf);
    pool_kernel<<<MROWS / 8, 256>>>(words, et);
    gemm_hmma_kernel<<<dim3(EMBED / NT, MROWS / MT), 256, SMEM_TOTAL>>>(bf, out);
}

// round 8
// speedup vs baseline: 1.4129x; 1.0444x over previous
#include <cuda_runtime.h>
#include <cuda_fp16.h>
#include <stdint.h>

#define VOCAB  30522
#define HIDDEN 768
#define EMBED  512
#define BATCH  16
#define SEQ    512
#define WSUB   4
#define MROWS  (BATCH*SEQ)     // 8192

#define BK     64              // k per stage (64 halves = 128B rows)
#define NCH    (HIDDEN/BK)     // 12 k-chunks
#define MT     128
#define NT     128
#define STAGES 3
#define A_ST   (MT*128)        // 16 KB
#define B_ST   (NT*128)        // 16 KB
#define STG_B  (A_ST + B_ST)   // 32 KB
#define SMEM_TOTAL (STAGES*STG_B + 128)

// ---- scratch (__device__ globals: allocation-free) ----
__device__ __align__(256) __half g_A [(size_t)MROWS*HIDDEN];   // pooled (ORIGINAL slots), fp16
__device__ __align__(256) __half g_Wt[(size_t)EMBED*HIDDEN];   // W^T  [N=512][K=768] fp16
__device__ int   g_src[MROWS];                                 // compacted row -> original row
__device__ int   g_lens[BATCH];
__device__ float g_padout[EMBED];

// ================= PTX helpers =================
__device__ __forceinline__ uint32_t smem_u32(const void* p) {
    uint32_t a;
    asm("{ .reg .u64 t; cvta.to.shared.u64 t, %1; cvt.u32.u64 %0, t; }" : "=r"(a) : "l"(p));
    return a;
}
#define CP16(dst, src)  asm volatile("cp.async.cg.shared.global [%0], [%1], 16;" :: "r"(dst), "l"(src))
#define CP_COMMIT()     asm volatile("cp.async.commit_group;" ::: "memory")
#define CP_WAIT2()      asm volatile("cp.async.wait_group 2;" ::: "memory")

__device__ __forceinline__ void ldsm_x4(uint32_t* r, uint32_t addr) {
    asm volatile("ldmatrix.sync.aligned.m8n8.x4.shared.b16 {%0,%1,%2,%3}, [%4];"
        : "=r"(r[0]), "=r"(r[1]), "=r"(r[2]), "=r"(r[3]) : "r"(addr));
}
__device__ __forceinline__ void mma16816(float* d, const uint32_t* a, uint32_t b0, uint32_t b1) {
    asm volatile("mma.sync.aligned.m16n8k16.row.col.f32.f16.f16.f32 "
        "{%0,%1,%2,%3}, {%4,%5,%6,%7}, {%8,%9}, {%0,%1,%2,%3};"
        : "+f"(d[0]), "+f"(d[1]), "+f"(d[2]), "+f"(d[3])
        : "r"(a[0]), "r"(a[1]), "r"(a[2]), "r"(a[3]), "r"(b0), "r"(b1));
}

// ============================================================
// Kernel 1 (fully fused prep): 4 independent roles, 512 thr/blk
//   [0,512)   : pool  — gather + masked mean -> g_A (original slot)
//   [512,528) : scan  — ballot prefix-sum -> g_src (inverse map), g_lens
//   [528,912) : wtrans — W [768][512] f32 -> g_Wt [512][768] f16
//   [912,928) : padout — leaky(embed[words[2047]] @ W + b)
// ============================================================
#define PREP_POOL   512
#define PREP_SCAN   (PREP_POOL + 16)
#define PREP_WT     (PREP_SCAN + 384)
#define PREP_BLKS   (PREP_WT + 16)

__global__ __launch_bounds__(512)
void prep_kernel(const int* __restrict__ words,
                 const float* __restrict__ et,
                 const float* __restrict__ Wf,
                 const float* __restrict__ bias) {
    const int bid = blockIdx.x, tid = threadIdx.x;

    if (bid < PREP_POOL) {
        // ---- pool: 16 warps, one word each, no compaction ----
        const int lane = tid & 31, w = tid >> 5;
        const int idx = bid * 16 + w;
        const int* wp = words + (size_t)idx * WSUB;
        const int i0 = wp[0], i1 = wp[1], i2 = wp[2], i3 = wp[3];
        const int cnt = (i0 != 0) + (i1 != 0) + (i2 != 0) + (i3 != 0);
        if (cnt == 0) return;
        const float inv = 1.0f / (float)cnt;

        const float* r0 = et + (size_t)i0 * HIDDEN + lane * 4;
        const float* r1 = et + (size_t)i1 * HIDDEN + lane * 4;
        const float* r2 = et + (size_t)i2 * HIDDEN + lane * 4;
        const float* r3 = et + (size_t)i3 * HIDDEN + lane * 4;

        float4 acc[6];
        #pragma unroll
        for (int c = 0; c < 6; c++) {
            float4 s = make_float4(0.f, 0.f, 0.f, 0.f);
            if (i0 != 0) { float4 v = *(const float4*)(r0 + c * 128); s.x += v.x; s.y += v.y; s.z += v.z; s.w += v.w; }
            if (i1 != 0) { float4 v = *(const float4*)(r1 + c * 128); s.x += v.x; s.y += v.y; s.z += v.z; s.w += v.w; }
            if (i2 != 0) { float4 v = *(const float4*)(r2 + c * 128); s.x += v.x; s.y += v.y; s.z += v.z; s.w += v.w; }
            if (i3 != 0) { float4 v = *(const float4*)(r3 + c * 128); s.x += v.x; s.y += v.y; s.z += v.z; s.w += v.w; }
            acc[c] = s;
        }
        __half* dst = g_A + (size_t)idx * HIDDEN + lane * 4;
        #pragma unroll
        for (int c = 0; c < 6; c++) {
            __half2 p0, p1;
            p0.x = __float2half(acc[c].x * inv); p0.y = __float2half(acc[c].y * inv);
            p1.x = __float2half(acc[c].z * inv); p1.y = __float2half(acc[c].w * inv);
            __half2* o = (__half2*)(dst + c * 128);
            o[0] = p0; o[1] = p1;
        }
    } else if (bid < PREP_SCAN) {
        // ---- scan: ballot prefix-sum, one batch per block ----
        __shared__ int ws[16];
        const int b = bid - PREP_POOL, s = tid;
        const int lane = tid & 31, w16 = tid >> 5;
        const int base = b * SEQ;
        const int* wp = words + ((size_t)(base + s)) * WSUB;
        int v = (wp[0] != 0) || (wp[1] != 0) || (wp[2] != 0) || (wp[3] != 0);
        g_src[base + s] = base;                       // default for tail slots
        unsigned m = __ballot_sync(0xFFFFFFFFu, v);
        int lanePre = __popc(m & ((1u << lane) - 1));
        if (lane == 0) ws[w16] = __popc(m);
        __syncthreads();
        if (tid < 16) {
            int x = ws[tid];
            #pragma unroll
            for (int off = 1; off < 16; off <<= 1) {
                int y = __shfl_up_sync(0xFFFFu, x, off);
                if (tid >= off) x += y;
            }
            ws[tid] = x;                               // inclusive
        }
        __syncthreads();
        const int excl = (w16 == 0) ? 0 : ws[w16 - 1];
        if (v) g_src[base + excl + lanePre] = base + s;
        if (tid == SEQ - 1) g_lens[b] = ws[15];
    } else if (bid < PREP_WT) {
        // ---- wtrans: 32x32 tile per block ----
        __shared__ float sh[32][33];
        const int b2 = bid - PREP_SCAN;
        const int ks = (b2 % (HIDDEN / 32)) * 32;
        const int ns = (b2 / (HIDDEN / 32)) * 32;
        const int tx = tid & 31, ty = tid >> 5;        // 32 x 16
        #pragma unroll
        for (int i = 0; i < 2; i++)
            sh[ty + 16 * i][tx] = Wf[(size_t)(ks + ty + 16 * i) * EMBED + ns + tx];
        __syncthreads();
        #pragma unroll
        for (int i = 0; i < 2; i++) {
            const int n = ns + ty + 16 * i, k = ks + tx;
            g_Wt[(size_t)n * HIDDEN + k] = __float2half(sh[tx][ty + 16 * i]);
        }
    } else {
        // ---- padout: 16 blocks, 32 cols x 16 k-slices of 48 ----
        __shared__ float part[16][33];
        const int pb = bid - PREP_WT;
        const int c = tid & 31, slice = tid >> 5;
        const int col = pb * 32 + c;
        const int pad_id = words[(SEQ - 1) * WSUB + (WSUB - 1)];
        const float* e = et + (size_t)pad_id * HIDDEN + slice * 48;
        const float* w = Wf + (size_t)(slice * 48) * EMBED + col;
        float p = 0.f;
        #pragma unroll
        for (int k = 0; k < 48; k++)
            p = fmaf(__ldg(e + k), __ldg(w + (size_t)k * EMBED), p);
        part[slice][c] = p;
        __syncthreads();
        if (slice == 0) {
            float s = 0.f;
            #pragma unroll
            for (int i = 0; i < 16; i++) s += part[i][c];
            float x = s + bias[col];
            g_padout[col] = (x >= 0.f) ? x : 0.1f * x;
        }
    }
}

// ============================================================
// Kernel 2: fp16 HMMA GEMM with row indirection + fused epilogue
// CTA 128x128, 8 warps (2x4) of 64x32, BK=64, 3-stage cp.async
// grid=(4,64), block=256, 2 CTAs/SM
// ============================================================
__device__ __forceinline__ void load_stage(int j, int tid, uint32_t data0,
                                           const int* s_src, int bn0) {
    const int s = j % STAGES;
    const int kk = j * BK;
    const uint32_t abase = data0 + s * STG_B;
    const uint32_t bbase = abase + A_ST;
    #pragma unroll
    for (int it = 0; it < 4; it++) {
        int c = tid + it * 256;
        int r = c >> 3, c16 = c & 7;
        const void* src = g_A + (size_t)s_src[r] * HIDDEN + kk + c16 * 8;
        uint32_t dst = abase + (uint32_t)(r * 128) + (((uint32_t)c16 * 16) ^ ((uint32_t)(r & 7) << 4));
        CP16(dst, src);
    }
    #pragma unroll
    for (int it = 0; it < 4; it++) {
        int c = tid + it * 256;
        int r = c >> 3, c16 = c & 7;
        const void* src = g_Wt + (size_t)(bn0 + r) * HIDDEN + kk + c16 * 8;
        uint32_t dst = bbase + (uint32_t)(r * 128) + (((uint32_t)c16 * 16) ^ ((uint32_t)(r & 7) << 4));
        CP16(dst, src);
    }
}

__global__ __launch_bounds__(256, 2)
void gemm_hmma_kernel(const float* __restrict__ bias, float* __restrict__ out) {
    extern __shared__ char smem[];
    __shared__ int s_src[MT];
    const uint32_t data0 = (smem_u32(smem) + 127u) & ~127u;
    const int tid = threadIdx.x, lane = tid & 31, wid = tid >> 5;
    const int wm = wid & 1, wn = wid >> 1;            // 2 x 4 warp grid
    const int bm0 = blockIdx.y * MT, bn0 = blockIdx.x * NT;

    // stage the row indirection for this M-tile
    if (tid < MT) s_src[tid] = g_src[bm0 + tid];
    __syncthreads();

    const int a_moff = (lane & 7) + ((lane >> 3) & 1) * 8;
    const int a_k8   = lane >> 4;
    const int b_noff = (lane & 7) + (lane >> 4) * 8;
    const int b_k8   = (lane >> 3) & 1;
    const uint32_t a_row = (uint32_t)((wm * 64 + a_moff) * 128);
    const uint32_t b_row = (uint32_t)(A_ST + (wn * 32 + b_noff) * 128);
    uint32_t akx[4], bkx[4];
    #pragma unroll
    for (int ks = 0; ks < 4; ks++) {
        akx[ks] = ((uint32_t)((ks * 2 + a_k8) * 16)) ^ ((uint32_t)(a_moff & 7) << 4);
        bkx[ks] = ((uint32_t)((ks * 2 + b_k8) * 16)) ^ ((uint32_t)(b_noff & 7) << 4);
    }

    float acc[4][4][4];
    #pragma unroll
    for (int i = 0; i < 4; i++)
        #pragma unroll
        for (int j = 0; j < 4; j++)
            #pragma unroll
            for (int q = 0; q < 4; q++) acc[i][j][q] = 0.f;

    load_stage(0, tid, data0, s_src, bn0); CP_COMMIT();
    load_stage(1, tid, data0, s_src, bn0); CP_COMMIT();

    for (int i = 0; i < NCH; i++) {
        if (i + 2 < NCH) load_stage(i + 2, tid, data0, s_src, bn0);
        CP_COMMIT();
        CP_WAIT2();
        __syncthreads();

        const uint32_t sa = data0 + (i % STAGES) * STG_B;
        #pragma unroll
        for (int ks = 0; ks < 4; ks++) {
            uint32_t a[4][4], b[2][4];
            #pragma unroll
            for (int mt = 0; mt < 4; mt++)
                ldsm_x4(a[mt], sa + a_row + (uint32_t)(mt * 2048) + akx[ks]);
            #pragma unroll
            for (int np = 0; np < 2; np++)
                ldsm_x4(b[np], sa + b_row + (uint32_t)(np * 2048) + bkx[ks]);
            #pragma unroll
            for (int mt = 0; mt < 4; mt++) {
                #pragma unroll
                for (int np = 0; np < 2; np++) {
                    mma16816(acc[mt][np * 2 + 0], a[mt], b[np][0], b[np][1]);
                    mma16816(acc[mt][np * 2 + 1], a[mt], b[np][2], b[np][3]);
                }
            }
        }
        __syncthreads();
    }

    // ---- epilogue: bias + leaky on valid rows, pad row on tail ----
    const int coln = bn0 + wn * 32 + (lane & 3) * 2;
    float2 bj[4], pj[4];
    #pragma unroll
    for (int nt = 0; nt < 4; nt++) {
        const int c = coln + nt * 8;
        bj[nt] = make_float2(__ldg(bias + c), __ldg(bias + c + 1));
        pj[nt] = make_float2(g_padout[c], g_padout[c + 1]);
    }
    #pragma unroll
    for (int mt = 0; mt < 4; mt++) {
        const int r0 = bm0 + wm * 64 + mt * 16 + (lane >> 2);
        const int len = g_lens[r0 >> 9];
        const bool v0 = (r0 & (SEQ - 1)) < len;
        const bool v1 = ((r0 + 8) & (SEQ - 1)) < len;
        #pragma unroll
        for (int nt = 0; nt < 4; nt++) {
            const int c = coln + nt * 8;
            float2 o0, o1;
            if (v0) {
                float x = acc[mt][nt][0] + bj[nt].x, y = acc[mt][nt][1] + bj[nt].y;
                o0 = make_float2(fmaxf(x, 0.1f * x), fmaxf(y, 0.1f * y));
            } else o0 = pj[nt];
            if (v1) {
                float x = acc[mt][nt][2] + bj[nt].x, y = acc[mt][nt][3] + bj[nt].y;
                o1 = make_float2(fmaxf(x, 0.1f * x), fmaxf(y, 0.1f * y));
            } else o1 = pj[nt];
            *(float2*)(out + (size_t)r0 * EMBED + c)       = o0;
            *(float2*)(out + (size_t)(r0 + 8) * EMBED + c) = o1;
        }
    }
}

// ============================================================
extern "C" void kernel_launch(void* const* d_in, const int* in_sizes, int n_in,
                              void* d_out, int out_size) {
    const int*   words = (const int*)  d_in[0];
    const float* et    = (const float*)d_in[1];
    const float* wf    = (const float*)d_in[2];
    const float* bf    = (const float*)d_in[3];
    float* out = (float*)d_out;

    cudaFuncSetAttribute(gemm_hmma_kernel,
                         cudaFuncAttributeMaxDynamicSharedMemorySize, SMEM_TOTAL);

    prep_kernel<<<PREP_BLKS, 512>>>(words, et, wf, bf);
    gemm_hmma_kernel<<<dim3(EMBED / NT, MROWS / MT), 256, SMEM_TOTAL>>>(bf, out);
}

// round 9
// speedup vs baseline: 1.4232x; 1.0073x over previous
#include <cuda_runtime.h>
#include <cuda_fp16.h>
#include <stdint.h>

#define VOCAB  30522
#define HIDDEN 768
#define EMBED  512
#define BATCH  16
#define SEQ    512
#define WSUB   4
#define MROWS  (BATCH*SEQ)     // 8192

#define BK     64              // k per stage (64 halves = 128B rows)
#define NCH    (HIDDEN/BK)     // 12 k-chunks
#define MT     128
#define NT     128
#define STAGES 3
#define A_ST   (MT*128)        // 16 KB
#define B_ST   (NT*128)        // 16 KB
#define STG_B  (A_ST + B_ST)   // 32 KB
#define SMEM_TOTAL (STAGES*STG_B + 128)

// ---- scratch (__device__ globals: allocation-free) ----
__device__ __align__(256) __half g_A [(size_t)MROWS*HIDDEN];   // pooled (ORIGINAL slots), fp16
__device__ __align__(256) __half g_Wt[(size_t)EMBED*HIDDEN];   // W^T  [N=512][K=768] fp16
__device__ int   g_src[MROWS];                                 // compacted row -> original row
__device__ int   g_lens[BATCH];
__device__ float g_padout[EMBED];

// ================= PTX helpers =================
__device__ __forceinline__ uint32_t smem_u32(const void* p) {
    uint32_t a;
    asm("{ .reg .u64 t; cvta.to.shared.u64 t, %1; cvt.u32.u64 %0, t; }" : "=r"(a) : "l"(p));
    return a;
}
#define CP16(dst, src)  asm volatile("cp.async.cg.shared.global [%0], [%1], 16;" :: "r"(dst), "l"(src))
#define CP_COMMIT()     asm volatile("cp.async.commit_group;" ::: "memory")
#define CP_WAIT2()      asm volatile("cp.async.wait_group 2;" ::: "memory")

__device__ __forceinline__ void ldsm_x4(uint32_t* r, uint32_t addr) {
    asm volatile("ldmatrix.sync.aligned.m8n8.x4.shared.b16 {%0,%1,%2,%3}, [%4];"
        : "=r"(r[0]), "=r"(r[1]), "=r"(r[2]), "=r"(r[3]) : "r"(addr));
}
__device__ __forceinline__ void mma16816(float* d, const uint32_t* a, uint32_t b0, uint32_t b1) {
    asm volatile("mma.sync.aligned.m16n8k16.row.col.f32.f16.f16.f32 "
        "{%0,%1,%2,%3}, {%4,%5,%6,%7}, {%8,%9}, {%0,%1,%2,%3};"
        : "+f"(d[0]), "+f"(d[1]), "+f"(d[2]), "+f"(d[3])
        : "r"(a[0]), "r"(a[1]), "r"(a[2]), "r"(a[3]), "r"(b0), "r"(b1));
}

// ============================================================
// Kernel 1 (fully fused prep): 4 independent roles, 512 thr/blk
//   [0,512)   : pool  — gather + masked mean -> g_A (original slot)
//   [512,528) : scan  — ballot prefix-sum -> g_src (inverse map), g_lens
//   [528,912) : wtrans — W [768][512] f32 -> g_Wt [512][768] f16
//   [912,928) : padout — leaky(embed[words[2047]] @ W + b)
// ============================================================
#define PREP_POOL   512
#define PREP_SCAN   (PREP_POOL + 16)
#define PREP_WT     (PREP_SCAN + 384)
#define PREP_BLKS   (PREP_WT + 16)

__global__ __launch_bounds__(512)
void prep_kernel(const int* __restrict__ words,
                 const float* __restrict__ et,
                 const float* __restrict__ Wf,
                 const float* __restrict__ bias) {
    const int bid = blockIdx.x, tid = threadIdx.x;

    if (bid < PREP_POOL) {
        // ---- pool: 16 warps, one word each, no compaction ----
        const int lane = tid & 31, w = tid >> 5;
        const int idx = bid * 16 + w;
        const int* wp = words + (size_t)idx * WSUB;
        const int i0 = wp[0], i1 = wp[1], i2 = wp[2], i3 = wp[3];
        const int cnt = (i0 != 0) + (i1 != 0) + (i2 != 0) + (i3 != 0);
        if (cnt == 0) return;
        const float inv = 1.0f / (float)cnt;

        const float* r0 = et + (size_t)i0 * HIDDEN + lane * 4;
        const float* r1 = et + (size_t)i1 * HIDDEN + lane * 4;
        const float* r2 = et + (size_t)i2 * HIDDEN + lane * 4;
        const float* r3 = et + (size_t)i3 * HIDDEN + lane * 4;

        float4 acc[6];
        #pragma unroll
        for (int c = 0; c < 6; c++) {
            float4 s = make_float4(0.f, 0.f, 0.f, 0.f);
            if (i0 != 0) { float4 v = *(const float4*)(r0 + c * 128); s.x += v.x; s.y += v.y; s.z += v.z; s.w += v.w; }
            if (i1 != 0) { float4 v = *(const float4*)(r1 + c * 128); s.x += v.x; s.y += v.y; s.z += v.z; s.w += v.w; }
            if (i2 != 0) { float4 v = *(const float4*)(r2 + c * 128); s.x += v.x; s.y += v.y; s.z += v.z; s.w += v.w; }
            if (i3 != 0) { float4 v = *(const float4*)(r3 + c * 128); s.x += v.x; s.y += v.y; s.z += v.z; s.w += v.w; }
            acc[c] = s;
        }
        __half* dst = g_A + (size_t)idx * HIDDEN + lane * 4;
        #pragma unroll
        for (int c = 0; c < 6; c++) {
            __half2 p0, p1;
            p0.x = __float2half(acc[c].x * inv); p0.y = __float2half(acc[c].y * inv);
            p1.x = __float2half(acc[c].z * inv); p1.y = __float2half(acc[c].w * inv);
            __half2* o = (__half2*)(dst + c * 128);
            o[0] = p0; o[1] = p1;
        }
    } else if (bid < PREP_SCAN) {
        // ---- scan: ballot prefix-sum, one batch per block ----
        __shared__ int ws[16];
        const int b = bid - PREP_POOL, s = tid;
        const int lane = tid & 31, w16 = tid >> 5;
        const int base = b * SEQ;
        const int* wp = words + ((size_t)(base + s)) * WSUB;
        int v = (wp[0] != 0) || (wp[1] != 0) || (wp[2] != 0) || (wp[3] != 0);
        g_src[base + s] = base;                       // default for tail slots
        unsigned m = __ballot_sync(0xFFFFFFFFu, v);
        int lanePre = __popc(m & ((1u << lane) - 1));
        if (lane == 0) ws[w16] = __popc(m);
        __syncthreads();
        if (tid < 16) {
            int x = ws[tid];
            #pragma unroll
            for (int off = 1; off < 16; off <<= 1) {
                int y = __shfl_up_sync(0xFFFFu, x, off);
                if (tid >= off) x += y;
            }
            ws[tid] = x;                               // inclusive
        }
        __syncthreads();
        const int excl = (w16 == 0) ? 0 : ws[w16 - 1];
        if (v) g_src[base + excl + lanePre] = base + s;
        if (tid == SEQ - 1) g_lens[b] = ws[15];
    } else if (bid < PREP_WT) {
        // ---- wtrans: 32x32 tile per block ----
        __shared__ float sh[32][33];
        const int b2 = bid - PREP_SCAN;
        const int ks = (b2 % (HIDDEN / 32)) * 32;
        const int ns = (b2 / (HIDDEN / 32)) * 32;
        const int tx = tid & 31, ty = tid >> 5;        // 32 x 16
        #pragma unroll
        for (int i = 0; i < 2; i++)
            sh[ty + 16 * i][tx] = Wf[(size_t)(ks + ty + 16 * i) * EMBED + ns + tx];
        __syncthreads();
        #pragma unroll
        for (int i = 0; i < 2; i++) {
            const int n = ns + ty + 16 * i, k = ks + tx;
            g_Wt[(size_t)n * HIDDEN + k] = __float2half(sh[tx][ty + 16 * i]);
        }
    } else {
        // ---- padout: 16 blocks, 32 cols x 16 k-slices of 48 ----
        __shared__ float part[16][33];
        const int pb = bid - PREP_WT;
        const int c = tid & 31, slice = tid >> 5;
        const int col = pb * 32 + c;
        const int pad_id = words[(SEQ - 1) * WSUB + (WSUB - 1)];
        const float* e = et + (size_t)pad_id * HIDDEN + slice * 48;
        const float* w = Wf + (size_t)(slice * 48) * EMBED + col;
        float p = 0.f;
        #pragma unroll
        for (int k = 0; k < 48; k++)
            p = fmaf(__ldg(e + k), __ldg(w + (size_t)k * EMBED), p);
        part[slice][c] = p;
        __syncthreads();
        if (slice == 0) {
            float s = 0.f;
            #pragma unroll
            for (int i = 0; i < 16; i++) s += part[i][c];
            float x = s + bias[col];
            g_padout[col] = (x >= 0.f) ? x : 0.1f * x;
        }
    }
}

// ============================================================
// Kernel 2: fp16 HMMA GEMM with row indirection + fused epilogue
// CTA 128x128, 8 warps (2x4) of 64x32, BK=64, 3-stage cp.async,
// register double-buffered ldmatrix pipeline.
// grid=(4,64), block=256, 2 CTAs/SM
// ============================================================
__device__ __forceinline__ void load_stage(int j, int tid, uint32_t data0,
                                           const int* s_src, int bn0) {
    const int s = j % STAGES;
    const int kk = j * BK;
    const uint32_t abase = data0 + s * STG_B;
    const uint32_t bbase = abase + A_ST;
    #pragma unroll
    for (int it = 0; it < 4; it++) {
        int c = tid + it * 256;
        int r = c >> 3, c16 = c & 7;
        const void* src = g_A + (size_t)s_src[r] * HIDDEN + kk + c16 * 8;
        uint32_t dst = abase + (uint32_t)(r * 128) + (((uint32_t)c16 * 16) ^ ((uint32_t)(r & 7) << 4));
        CP16(dst, src);
    }
    #pragma unroll
    for (int it = 0; it < 4; it++) {
        int c = tid + it * 256;
        int r = c >> 3, c16 = c & 7;
        const void* src = g_Wt + (size_t)(bn0 + r) * HIDDEN + kk + c16 * 8;
        uint32_t dst = bbase + (uint32_t)(r * 128) + (((uint32_t)c16 * 16) ^ ((uint32_t)(r & 7) << 4));
        CP16(dst, src);
    }
}

__global__ __launch_bounds__(256, 2)
void gemm_hmma_kernel(const float* __restrict__ bias, float* __restrict__ out) {
    extern __shared__ char smem[];
    __shared__ int s_src[MT];
    const uint32_t data0 = (smem_u32(smem) + 127u) & ~127u;
    const int tid = threadIdx.x, lane = tid & 31, wid = tid >> 5;
    const int wm = wid & 1, wn = wid >> 1;            // 2 x 4 warp grid
    const int bm0 = blockIdx.y * MT, bn0 = blockIdx.x * NT;

    if (tid < MT) s_src[tid] = g_src[bm0 + tid];
    __syncthreads();

    const int a_moff = (lane & 7) + ((lane >> 3) & 1) * 8;
    const int a_k8   = lane >> 4;
    const int b_noff = (lane & 7) + (lane >> 4) * 8;
    const int b_k8   = (lane >> 3) & 1;
    const uint32_t a_row = (uint32_t)((wm * 64 + a_moff) * 128);
    const uint32_t b_row = (uint32_t)(A_ST + (wn * 32 + b_noff) * 128);
    uint32_t akx[4], bkx[4];
    #pragma unroll
    for (int ks = 0; ks < 4; ks++) {
        akx[ks] = ((uint32_t)((ks * 2 + a_k8) * 16)) ^ ((uint32_t)(a_moff & 7) << 4);
        bkx[ks] = ((uint32_t)((ks * 2 + b_k8) * 16)) ^ ((uint32_t)(b_noff & 7) << 4);
    }

    float acc[4][4][4];
    #pragma unroll
    for (int i = 0; i < 4; i++)
        #pragma unroll
        for (int j = 0; j < 4; j++)
            #pragma unroll
            for (int q = 0; q < 4; q++) acc[i][j][q] = 0.f;

    load_stage(0, tid, data0, s_src, bn0); CP_COMMIT();
    load_stage(1, tid, data0, s_src, bn0); CP_COMMIT();

    // double-buffered fragments
    uint32_t a[2][4][4], b[2][2][4];

    for (int i = 0; i < NCH; i++) {
        if (i + 2 < NCH) load_stage(i + 2, tid, data0, s_src, bn0);
        CP_COMMIT();
        CP_WAIT2();
        __syncthreads();

        const uint32_t sa = data0 + (i % STAGES) * STG_B;

        // prime ks=0 into buffer 0
        #pragma unroll
        for (int mt = 0; mt < 4; mt++)
            ldsm_x4(a[0][mt], sa + a_row + (uint32_t)(mt * 2048) + akx[0]);
        #pragma unroll
        for (int np = 0; np < 2; np++)
            ldsm_x4(b[0][np], sa + b_row + (uint32_t)(np * 2048) + bkx[0]);

        #pragma unroll
        for (int ks = 0; ks < 4; ks++) {
            const int cb = ks & 1, nb = cb ^ 1;
            if (ks < 3) {    // prefetch ks+1 while computing ks
                #pragma unroll
                for (int mt = 0; mt < 4; mt++)
                    ldsm_x4(a[nb][mt], sa + a_row + (uint32_t)(mt * 2048) + akx[ks + 1]);
                #pragma unroll
                for (int np = 0; np < 2; np++)
                    ldsm_x4(b[nb][np], sa + b_row + (uint32_t)(np * 2048) + bkx[ks + 1]);
            }
            #pragma unroll
            for (int mt = 0; mt < 4; mt++) {
                #pragma unroll
                for (int np = 0; np < 2; np++) {
                    mma16816(acc[mt][np * 2 + 0], a[cb][mt], b[cb][np][0], b[cb][np][1]);
                    mma16816(acc[mt][np * 2 + 1], a[cb][mt], b[cb][np][2], b[cb][np][3]);
                }
            }
        }
        __syncthreads();
    }

    // ---- epilogue: bias + leaky on valid rows, pad row on tail ----
    const int coln = bn0 + wn * 32 + (lane & 3) * 2;
    float2 bj[4], pj[4];
    #pragma unroll
    for (int nt = 0; nt < 4; nt++) {
        const int c = coln + nt * 8;
        bj[nt] = make_float2(__ldg(bias + c), __ldg(bias + c + 1));
        pj[nt] = make_float2(g_padout[c], g_padout[c + 1]);
    }
    #pragma unroll
    for (int mt = 0; mt < 4; mt++) {
        const int r0 = bm0 + wm * 64 + mt * 16 + (lane >> 2);
        const int len = g_lens[r0 >> 9];
        const bool v0 = (r0 & (SEQ - 1)) < len;
        const bool v1 = ((r0 + 8) & (SEQ - 1)) < len;
        #pragma unroll
        for (int nt = 0; nt < 4; nt++) {
            const int c = coln + nt * 8;
            float2 o0, o1;
            if (v0) {
                float x = acc[mt][nt][0] + bj[nt].x, y = acc[mt][nt][1] + bj[nt].y;
                o0 = make_float2(fmaxf(x, 0.1f * x), fmaxf(y, 0.1f * y));
            } else o0 = pj[nt];
            if (v1) {
                float x = acc[mt][nt][2] + bj[nt].x, y = acc[mt][nt][3] + bj[nt].y;
                o1 = make_float2(fmaxf(x, 0.1f * x), fmaxf(y, 0.1f * y));
            } else o1 = pj[nt];
            *(float2*)(out + (size_t)r0 * EMBED + c)       = o0;
            *(float2*)(out + (size_t)(r0 + 8) * EMBED + c) = o1;
        }
    }
}

// ============================================================
extern "C" void kernel_launch(void* const* d_in, const int* in_sizes, int n_in,
                              void* d_out, int out_size) {
    const int*   words = (const int*)  d_in[0];
    const float* et    = (const float*)d_in[1];
    const float* wf    = (const float*)d_in[2];
    const float* bf    = (const float*)d_in[3];
    float* out = (float*)d_out;

    cudaFuncSetAttribute(gemm_hmma_kernel,
                         cudaFuncAttributeMaxDynamicSharedMemorySize, SMEM_TOTAL);

    prep_kernel<<<PREP_BLKS, 512>>>(words, et, wf, bf);
    gemm_hmma_kernel<<<dim3(EMBED / NT, MROWS / MT), 256, SMEM_TOTAL>>>(bf, out);
}